// round 1
// baseline (speedup 1.0000x reference)
#include <cuda_runtime.h>
#include <math.h>

#define BB 8
#define C 64
#define CO 128
#define H 128
#define W 128
#define HW (H*W)
#define TAPS 9
#define KK (C*TAPS)      // 576
#define PXT 64           // pixel tile: 2 rows x 32 cols
#define KC 64            // K chunk for weight staging
#define EPSV 1e-5f

// ------------------------- scratch (device globals; no allocation) -----------
__device__ float g_t[BB*2*C*HW];     // conv1 out: ch<64 = off branch, >=64 = mod branch
__device__ float g_act[BB*2*C*HW];   // silu(bn(g_t))
__device__ float g_offs[BB*18*HW];   // offset field
__device__ float g_modu[BB*9*HW];    // sigmoid modulation
__device__ float g_scale[2*C];
__device__ float g_shift[2*C];
__device__ float g_wt1[KK*CO];       // conv1 weights transposed [(c*9+t)][co]
__device__ float g_wt4[KK*CO];       // main weight transposed  [(c*9+t)][o]

// ------------------------- weight transpose prep -----------------------------
__global__ void prep_weights(const float* __restrict__ off_w1,
                             const float* __restrict__ mod_w1,
                             const float* __restrict__ wmain) {
    int i = blockIdx.x * blockDim.x + threadIdx.x;
    if (i >= KK*CO) return;
    int k = i >> 7, co = i & 127;
    int c = k / 9, t = k - c * 9;
    float w1 = (co < 64) ? off_w1[(co*C + c)*9 + t]
                         : mod_w1[((co-64)*C + c)*9 + t];
    g_wt1[i] = w1;
    g_wt4[i] = wmain[(co*C + c)*9 + t];
}

// ------------------------- fused conv1 (both branches as one M=128 GEMM) ----
extern __shared__ float smem_dyn[];

__global__ __launch_bounds__(256) void conv1_kernel(const float* __restrict__ x,
                                                    const float* __restrict__ b_off,
                                                    const float* __restrict__ b_mod) {
    float* sS = smem_dyn;                 // [KK][PXT]
    float* sW = smem_dyn + KK*PXT;        // [KC][CO]

    int tile = blockIdx.x;                // 2048 tiles
    int b  = tile >> 8;                   // 256 tiles per image
    int r  = tile & 255;
    int h0 = (r >> 2) * 2;
    int w0 = (r & 3) * 32;
    int tid = threadIdx.x;
    const float* xb = x + (size_t)b * C * HW;

    // Phase A: im2col into smem
    for (int i = tid; i < KK*PXT; i += 256) {
        int k = i >> 6, px = i & 63;
        int c = k / 9, t = k - c * 9;
        int dy = t / 3 - 1, dx = t - (t/3)*3 - 1;
        int hh = h0 + (px >> 5) + dy;
        int ww = w0 + (px & 31) + dx;
        float v = 0.f;
        if ((unsigned)hh < H && (unsigned)ww < W)
            v = __ldg(xb + c*HW + hh*W + ww);
        sS[k*PXT + px] = v;
    }

    int tpx = tid & 15;     // px base = tpx*4
    int tco = tid >> 4;     // co base = tco*8
    float acc[8][4];
    #pragma unroll
    for (int i = 0; i < 8; i++)
        #pragma unroll
        for (int j = 0; j < 4; j++) acc[i][j] = 0.f;

    for (int kc = 0; kc < KK; kc += KC) {
        __syncthreads();
        const float4* gsrc = (const float4*)(g_wt1 + kc*CO);
        float4* wdst = (float4*)sW;
        for (int i = tid; i < KC*CO/4; i += 256) wdst[i] = gsrc[i];
        __syncthreads();
        #pragma unroll 8
        for (int kk = 0; kk < KC; kk++) {
            float4 s  = *(const float4*)(sS + (size_t)(kc+kk)*PXT + tpx*4);
            float4 wa = *(const float4*)(sW + kk*CO + tco*8);
            float4 wb = *(const float4*)(sW + kk*CO + tco*8 + 4);
            float sv[4] = {s.x, s.y, s.z, s.w};
            float wv[8] = {wa.x, wa.y, wa.z, wa.w, wb.x, wb.y, wb.z, wb.w};
            #pragma unroll
            for (int i = 0; i < 8; i++)
                #pragma unroll
                for (int j = 0; j < 4; j++)
                    acc[i][j] = fmaf(wv[i], sv[j], acc[i][j]);
        }
    }

    int px0 = tpx * 4;
    int hh = h0 + (px0 >> 5), ww = w0 + (px0 & 31);
    #pragma unroll
    for (int i = 0; i < 8; i++) {
        int co = tco*8 + i;
        float bbv = (co < 64) ? __ldg(b_off + co) : __ldg(b_mod + co - 64);
        float4 o = make_float4(acc[i][0]+bbv, acc[i][1]+bbv, acc[i][2]+bbv, acc[i][3]+bbv);
        *(float4*)(g_t + ((size_t)(b*2*C + co))*HW + hh*W + ww) = o;
    }
}

// ------------------------- BN stats (one block per channel) ------------------
__inline__ __device__ float warpsum(float v) {
    #pragma unroll
    for (int o = 16; o; o >>= 1) v += __shfl_down_sync(0xFFFFFFFFu, v, o);
    return v;
}

__global__ __launch_bounds__(256) void bn_stats(const float* __restrict__ gam_off,
                                                const float* __restrict__ bet_off,
                                                const float* __restrict__ gam_mod,
                                                const float* __restrict__ bet_mod) {
    int ch = blockIdx.x;   // 0..127
    int tid = threadIdx.x;
    float s = 0.f, s2 = 0.f;
    for (int b = 0; b < BB; b++) {
        const float4* p = (const float4*)(g_t + ((size_t)(b*2*C + ch))*HW);
        for (int i = tid; i < HW/4; i += 256) {
            float4 v = p[i];
            s  += v.x + v.y + v.z + v.w;
            s2 += v.x*v.x + v.y*v.y + v.z*v.z + v.w*v.w;
        }
    }
    __shared__ float rs[8], rs2[8];
    int lane = tid & 31, wid = tid >> 5;
    s = warpsum(s); s2 = warpsum(s2);
    if (lane == 0) { rs[wid] = s; rs2[wid] = s2; }
    __syncthreads();
    if (wid == 0) {
        s  = (lane < 8) ? rs[lane]  : 0.f;
        s2 = (lane < 8) ? rs2[lane] : 0.f;
        s = warpsum(s); s2 = warpsum(s2);
        if (lane == 0) {
            float n = (float)(BB*HW);
            float m = s / n;
            float var = s2 / n - m*m;
            float ga = (ch < 64) ? __ldg(gam_off + ch) : __ldg(gam_mod + ch - 64);
            float be = (ch < 64) ? __ldg(bet_off + ch) : __ldg(bet_mod + ch - 64);
            float sc = ga * rsqrtf(var + EPSV);
            g_scale[ch] = sc;
            g_shift[ch] = be - m * sc;
        }
    }
}

// ------------------------- BN apply + SiLU -----------------------------------
__global__ __launch_bounds__(256) void bn_act_kernel() {
    int n4 = BB*2*C*HW/4;
    for (int i = blockIdx.x*blockDim.x + threadIdx.x; i < n4; i += gridDim.x*blockDim.x) {
        int c = (i >> 12) & 127;   // HW/4 = 4096
        float sc = g_scale[c], sh = g_shift[c];
        float4 v = ((const float4*)g_t)[i];
        v.x = v.x*sc + sh; v.y = v.y*sc + sh; v.z = v.z*sc + sh; v.w = v.w*sc + sh;
        v.x = __fdividef(v.x, 1.f + __expf(-v.x));
        v.y = __fdividef(v.y, 1.f + __expf(-v.y));
        v.z = __fdividef(v.z, 1.f + __expf(-v.z));
        v.w = __fdividef(v.w, 1.f + __expf(-v.w));
        ((float4*)g_act)[i] = v;
    }
}

// ------------------------- conv2 (direct, 4-px register tile) ----------------
template<int NCO, bool SIG>
__global__ __launch_bounds__(256) void conv2_kernel(int chbase,
                                                    const float* __restrict__ wt,
                                                    const float* __restrict__ bs,
                                                    float* __restrict__ outbuf) {
    int g = blockIdx.x * blockDim.x + threadIdx.x;  // 32768 groups
    int b   = g >> 12;
    int rem = g & 4095;
    int h   = rem >> 5;
    int w0  = (rem & 31) * 4;
    const float* ab = g_act + ((size_t)b*2*C + chbase)*HW;

    float acc[NCO][4];
    #pragma unroll
    for (int co = 0; co < NCO; co++) {
        float bv = __ldg(bs + co);
        #pragma unroll
        for (int j = 0; j < 4; j++) acc[co][j] = bv;
    }

    for (int c = 0; c < C; c++) {
        const float* p = ab + c*HW;
        float xv[3][6];
        #pragma unroll
        for (int rr = 0; rr < 3; rr++) {
            int hh = h + rr - 1;
            bool hv = (unsigned)hh < H;
            #pragma unroll
            for (int j = 0; j < 6; j++) {
                int ww = w0 + j - 1;
                xv[rr][j] = (hv && (unsigned)ww < W) ? __ldg(p + hh*W + ww) : 0.f;
            }
        }
        #pragma unroll
        for (int co = 0; co < NCO; co++) {
            const float* wp = wt + (co*C + c)*9;
            #pragma unroll
            for (int t = 0; t < 9; t++) {
                float wv = __ldg(wp + t);
                int rr = t / 3, dc = t - rr*3;
                #pragma unroll
                for (int j = 0; j < 4; j++)
                    acc[co][j] = fmaf(wv, xv[rr][dc + j], acc[co][j]);
            }
        }
    }
    #pragma unroll
    for (int co = 0; co < NCO; co++) {
        float4 o;
        float* a = acc[co];
        if (SIG) {
            a[0] = __fdividef(1.f, 1.f + __expf(-a[0]));
            a[1] = __fdividef(1.f, 1.f + __expf(-a[1]));
            a[2] = __fdividef(1.f, 1.f + __expf(-a[2]));
            a[3] = __fdividef(1.f, 1.f + __expf(-a[3]));
        }
        o = make_float4(a[0], a[1], a[2], a[3]);
        *(float4*)(outbuf + ((size_t)(b*NCO + co))*HW + h*W + w0) = o;
    }
}

// ------------------------- deformable sample + main GEMM ---------------------
__global__ __launch_bounds__(256) void deform_kernel(const float* __restrict__ x,
                                                     const float* __restrict__ bias,
                                                     float* __restrict__ out) {
    float* sS   = smem_dyn;                        // [KK][PXT]
    float* sW   = smem_dyn + KK*PXT;               // [KC][CO]
    float* sWgt = smem_dyn + KK*PXT + KC*CO;       // [TAPS][4][PXT]
    int*   sIdx = (int*)(sWgt + TAPS*4*PXT);       // [TAPS][4][PXT]

    int tile = blockIdx.x;
    int b  = tile >> 8;
    int r  = tile & 255;
    int h0 = (r >> 2) * 2;
    int w0 = (r & 3) * 32;
    int tid = threadIdx.x;
    const float* xb = x + (size_t)b * C * HW;

    // Phase A0: per-(tap, px) bilinear corners & weights (incl. modulation)
    for (int i = tid; i < TAPS*PXT; i += 256) {
        int tap = i >> 6, px = i & 63;
        int hh = h0 + (px >> 5), ww = w0 + (px & 31);
        size_t sp = (size_t)hh*W + ww;
        float offy = __ldg(g_offs + ((size_t)(b*18 + tap*2 + 1))*HW + sp);
        float offx = __ldg(g_offs + ((size_t)(b*18 + tap*2 + 0))*HW + sp);
        float m    = __ldg(g_modu + ((size_t)(b*9 + tap))*HW + sp);
        float sy = (float)hh + (float)(tap/3 - 1) + offy;
        float sx = (float)ww + (float)(tap%3 - 1) + offx;
        float y0f = floorf(sy), x0f = floorf(sx);
        int y0 = (int)y0f, x0 = (int)x0f;
        float wy1 = sy - y0f, wx1 = sx - x0f;
        float wy0 = 1.f - wy1, wx0 = 1.f - wx1;
        #pragma unroll
        for (int cn = 0; cn < 4; cn++) {
            int yy = y0 + (cn >> 1);
            int xx = x0 + (cn & 1);
            float wgt = ((cn & 2) ? wy1 : wy0) * ((cn & 1) ? wx1 : wx0) * m;
            bool valid = ((unsigned)yy < H) && ((unsigned)xx < W);
            sWgt[(tap*4 + cn)*PXT + px] = valid ? wgt : 0.f;
            int yc = min(max(yy, 0), H-1);
            int xc = min(max(xx, 0), W-1);
            sIdx[(tap*4 + cn)*PXT + px] = yc*W + xc;
        }
    }
    __syncthreads();

    // Phase A1: gather sampled matrix S[c*9+t][px]
    for (int i = tid; i < KK*PXT; i += 256) {
        int k = i >> 6, px = i & 63;
        int c = k / 9, t = k - c*9;
        const float* xc = xb + c*HW;
        float v = sWgt[(t*4+0)*PXT + px] * __ldg(xc + sIdx[(t*4+0)*PXT + px]);
        v = fmaf(sWgt[(t*4+1)*PXT + px], __ldg(xc + sIdx[(t*4+1)*PXT + px]), v);
        v = fmaf(sWgt[(t*4+2)*PXT + px], __ldg(xc + sIdx[(t*4+2)*PXT + px]), v);
        v = fmaf(sWgt[(t*4+3)*PXT + px], __ldg(xc + sIdx[(t*4+3)*PXT + px]), v);
        sS[k*PXT + px] = v;
    }

    int tpx = tid & 15;
    int tco = tid >> 4;
    float acc[8][4];
    #pragma unroll
    for (int i = 0; i < 8; i++)
        #pragma unroll
        for (int j = 0; j < 4; j++) acc[i][j] = 0.f;

    for (int kc = 0; kc < KK; kc += KC) {
        __syncthreads();
        const float4* gsrc = (const float4*)(g_wt4 + kc*CO);
        float4* wdst = (float4*)sW;
        for (int i = tid; i < KC*CO/4; i += 256) wdst[i] = gsrc[i];
        __syncthreads();
        #pragma unroll 8
        for (int kk = 0; kk < KC; kk++) {
            float4 s  = *(const float4*)(sS + (size_t)(kc+kk)*PXT + tpx*4);
            float4 wa = *(const float4*)(sW + kk*CO + tco*8);
            float4 wb = *(const float4*)(sW + kk*CO + tco*8 + 4);
            float sv[4] = {s.x, s.y, s.z, s.w};
            float wv[8] = {wa.x, wa.y, wa.z, wa.w, wb.x, wb.y, wb.z, wb.w};
            #pragma unroll
            for (int i = 0; i < 8; i++)
                #pragma unroll
                for (int j = 0; j < 4; j++)
                    acc[i][j] = fmaf(wv[i], sv[j], acc[i][j]);
        }
    }

    int px0 = tpx * 4;
    int hh = h0 + (px0 >> 5), ww = w0 + (px0 & 31);
    #pragma unroll
    for (int i = 0; i < 8; i++) {
        int co = tco*8 + i;
        float bbv = __ldg(bias + co);
        float4 o = make_float4(acc[i][0]+bbv, acc[i][1]+bbv, acc[i][2]+bbv, acc[i][3]+bbv);
        *(float4*)(out + ((size_t)(b*CO + co))*HW + hh*W + ww) = o;
    }
}

// ------------------------- launch ---------------------------------------------
extern "C" void kernel_launch(void* const* d_in, const int* in_sizes, int n_in,
                              void* d_out, int out_size) {
    const float* x        = (const float*)d_in[0];
    const float* weight   = (const float*)d_in[1];
    const float* bias     = (const float*)d_in[2];
    const float* off_w1   = (const float*)d_in[3];
    const float* off_b1   = (const float*)d_in[4];
    const float* off_g    = (const float*)d_in[5];
    const float* off_be   = (const float*)d_in[6];
    const float* off_w2   = (const float*)d_in[7];
    const float* off_b2   = (const float*)d_in[8];
    const float* mod_w1   = (const float*)d_in[9];
    const float* mod_b1   = (const float*)d_in[10];
    const float* mod_g    = (const float*)d_in[11];
    const float* mod_be   = (const float*)d_in[12];
    const float* mod_w2   = (const float*)d_in[13];
    const float* mod_b2   = (const float*)d_in[14];
    float* out = (float*)d_out;

    const int smem_conv1  = (KK*PXT + KC*CO) * 4;                     // 180224
    const int smem_deform = (KK*PXT + KC*CO + TAPS*4*PXT)*4 + TAPS*4*PXT*4; // 198656
    cudaFuncSetAttribute(conv1_kernel,  cudaFuncAttributeMaxDynamicSharedMemorySize, smem_conv1);
    cudaFuncSetAttribute(deform_kernel, cudaFuncAttributeMaxDynamicSharedMemorySize, smem_deform);

    // pointers to device-global scratch for conv2 outputs
    float *offs_ptr, *modu_ptr;
    cudaGetSymbolAddress((void**)&offs_ptr, g_offs);
    cudaGetSymbolAddress((void**)&modu_ptr, g_modu);

    prep_weights<<<(KK*CO + 255)/256, 256>>>(off_w1, mod_w1, weight);
    conv1_kernel<<<2048, 256, smem_conv1>>>(x, off_b1, mod_b1);
    bn_stats<<<128, 256>>>(off_g, off_be, mod_g, mod_be);
    bn_act_kernel<<<8192, 256>>>();
    conv2_kernel<18, false><<<128, 256>>>(0,  off_w2, off_b2, offs_ptr);
    conv2_kernel<9,  true ><<<128, 256>>>(64, mod_w2, mod_b2, modu_ptr);
    deform_kernel<<<2048, 256, smem_deform>>>(x, bias, out);
}

// round 5
// speedup vs baseline: 1.2490x; 1.2490x over previous
#include <cuda_runtime.h>
#include <cuda_bf16.h>
#include <math.h>
#include <stdint.h>

#define BB 8
#define C 64
#define COUT 128
#define H 128
#define W 128
#define HW (H*W)
#define KC 64
#define NCHUNK 9
#define SK 72              // smem k-stride (bf16 elems): 144B rows
#define EPSV 1e-5f

// ---------------- smem layout (byte offsets) ----------------
#define OFF_AHI 0
#define OFF_ALO 18432
#define OFF_BHI 36864
#define OFF_BLO 55296
#define SMEM_GEMM 73728
#define OFF_TAPW 73728                 // deform: float [36][128]
#define OFF_TAPI (73728 + 18432)       // deform: int   [36][128]
#define SMEM_DEF  (OFF_TAPI + 18432)   // 110592

// ---------------- device scratch ----------------
__device__ float g_t[BB*2*C*HW];
__device__ float g_act[BB*2*C*HW];
__device__ float g_offs[BB*18*HW];
__device__ float g_modu[BB*9*HW];
__device__ float g_scale[2*C];
__device__ float g_shift[2*C];
// per-chunk weight tiles [NCHUNK][128 co][SK] bf16 (k pad 64..71 unread)
__device__ __align__(16) unsigned short g_w1h[NCHUNK*COUT*SK];
__device__ __align__(16) unsigned short g_w1l[NCHUNK*COUT*SK];
__device__ __align__(16) unsigned short g_w4h[NCHUNK*COUT*SK];
__device__ __align__(16) unsigned short g_w4l[NCHUNK*COUT*SK];

// ---------------- helpers ----------------
__device__ __forceinline__ uint32_t smem_u32(const void* p) {
    uint32_t a;
    asm("{ .reg .u64 t; cvta.to.shared.u64 t, %1; cvt.u32.u64 %0, t; }" : "=r"(a) : "l"(p));
    return a;
}
__device__ __forceinline__ void split_bf(float v, unsigned short& hb, unsigned short& lb) {
    __nv_bfloat16 h = __float2bfloat16(v);
    float r = v - __bfloat162float(h);
    __nv_bfloat16 l = __float2bfloat16(r);
    hb = *reinterpret_cast<unsigned short*>(&h);
    lb = *reinterpret_cast<unsigned short*>(&l);
}
__device__ __forceinline__ void ldsm_x4(uint32_t a[4], uint32_t addr) {
    asm volatile("ldmatrix.sync.aligned.m8n8.x4.shared.b16 {%0,%1,%2,%3}, [%4];"
        : "=r"(a[0]), "=r"(a[1]), "=r"(a[2]), "=r"(a[3]) : "r"(addr));
}
__device__ __forceinline__ void ldsm_x2(uint32_t b[2], uint32_t addr) {
    asm volatile("ldmatrix.sync.aligned.m8n8.x2.shared.b16 {%0,%1}, [%2];"
        : "=r"(b[0]), "=r"(b[1]) : "r"(addr));
}
__device__ __forceinline__ void mma_bf16(float d[4], const uint32_t a[4], const uint32_t b[2]) {
    asm volatile("mma.sync.aligned.m16n8k16.row.col.f32.bf16.bf16.f32 "
        "{%0,%1,%2,%3}, {%4,%5,%6,%7}, {%8,%9}, {%0,%1,%2,%3};"
        : "+f"(d[0]), "+f"(d[1]), "+f"(d[2]), "+f"(d[3])
        : "r"(a[0]), "r"(a[1]), "r"(a[2]), "r"(a[3]), "r"(b[0]), "r"(b[1]));
}
// ldmatrix source addresses (per-lane)
__device__ __forceinline__ uint32_t a_addr(uint32_t base, int row0, int k0, int lane) {
    int q = lane >> 3;
    int row = row0 + (lane & 7) + (q & 1) * 8;
    int col = k0 + (q >> 1) * 8;
    return base + (uint32_t)(row * SK + col) * 2u;
}
__device__ __forceinline__ uint32_t b_addr(uint32_t base, int row0, int k0, int lane) {
    int l = lane & 15;
    int row = row0 + (l & 7);
    int col = k0 + (l >> 3) * 8;
    return base + (uint32_t)(row * SK + col) * 2u;
}

// ---------------- weight prep: split into [ck][co][k] tiles ----------------
__global__ void prep_weights(const float* __restrict__ off_w1,
                             const float* __restrict__ mod_w1,
                             const float* __restrict__ wmain) {
    int i = blockIdx.x * 256 + threadIdx.x;
    if (i >= NCHUNK*COUT*KC) return;
    int ck = i / (COUT*KC);
    int r  = i - ck*(COUT*KC);
    int co = r >> 6;
    int j  = r & 63;
    int k = ck*KC + j;
    int c = k / 9, t = k - c*9;
    size_t soff = (size_t)(ck*COUT + co)*SK + j;
    float w1 = (co < 64) ? off_w1[(co*C + c)*9 + t] : mod_w1[((co-64)*C + c)*9 + t];
    unsigned short hb, lb;
    split_bf(w1, hb, lb);
    g_w1h[soff] = hb; g_w1l[soff] = lb;
    float w4 = wmain[(co*C + c)*9 + t];
    split_bf(w4, hb, lb);
    g_w4h[soff] = hb; g_w4l[soff] = lb;
}

extern __shared__ char smem_dyn[];

// ---------------- shared GEMM consumer: one KC-chunk of MMAs ----------------
__device__ __forceinline__ void mma_chunk(uint32_t smem_base, int lane, int wco, int wpx,
                                          float acc[2][8][4]) {
    uint32_t baseAh = smem_base + OFF_AHI;
    uint32_t baseAl = smem_base + OFF_ALO;
    uint32_t baseBh = smem_base + OFF_BHI;
    uint32_t baseBl = smem_base + OFF_BLO;
    #pragma unroll
    for (int ks = 0; ks < 4; ks++) {
        int k0 = ks * 16;
        uint32_t ah[2][4], al[2][4];
        #pragma unroll
        for (int mt = 0; mt < 2; mt++) {
            ldsm_x4(ah[mt], a_addr(baseAh, wco + mt*16, k0, lane));
            ldsm_x4(al[mt], a_addr(baseAl, wco + mt*16, k0, lane));
        }
        #pragma unroll
        for (int nt = 0; nt < 8; nt++) {
            uint32_t bh[2], bl[2];
            ldsm_x2(bh, b_addr(baseBh, wpx + nt*8, k0, lane));
            ldsm_x2(bl, b_addr(baseBl, wpx + nt*8, k0, lane));
            #pragma unroll
            for (int mt = 0; mt < 2; mt++) {
                mma_bf16(acc[mt][nt], ah[mt], bh);
                mma_bf16(acc[mt][nt], ah[mt], bl);
                mma_bf16(acc[mt][nt], al[mt], bh);
            }
        }
    }
}

// ---------------- conv1: mma GEMM, im2col producer ----------------
__global__ __launch_bounds__(256) void conv1_t(const float* __restrict__ x,
                                               const float* __restrict__ b_off,
                                               const float* __restrict__ b_mod) {
    char* smem_c = smem_dyn;
    uint32_t smem_base = smem_u32(smem_c);
    int tid = threadIdx.x, wid = tid >> 5, lane = tid & 31;
    int blk = blockIdx.x;
    int b = blk >> 7, h = blk & 127;
    const float* xb = x + (size_t)b * C * HW;

    int wco = (wid >> 1) * 32;
    int wpx = (wid & 1) * 64;
    float acc[2][8][4];
    #pragma unroll
    for (int mt = 0; mt < 2; mt++)
        #pragma unroll
        for (int nt = 0; nt < 8; nt++)
            #pragma unroll
            for (int q = 0; q < 4; q++) acc[mt][nt][q] = 0.f;

    for (int ck = 0; ck < NCHUNK; ck++) {
        if (ck) __syncthreads();
        // A tiles (pre-split weights)
        {
            const uint4* sh = (const uint4*)(g_w1h + (size_t)ck*COUT*SK);
            const uint4* sl = (const uint4*)(g_w1l + (size_t)ck*COUT*SK);
            uint4* dh = (uint4*)(smem_c + OFF_AHI);
            uint4* dl = (uint4*)(smem_c + OFF_ALO);
            for (int i = tid; i < COUT*SK/8; i += 256) { dh[i] = sh[i]; dl[i] = sl[i]; }
        }
        // B tiles: im2col + split, rows px, stride SK
        #pragma unroll
        for (int pass = 0; pass < 4; pass++) {
            int it = pass*256 + tid;
            int px = it >> 3, jg = it & 7;
            unsigned short hb[8], lb[8];
            #pragma unroll
            for (int jj = 0; jj < 8; jj++) {
                int k = ck*KC + jg*8 + jj;
                int c = k / 9, t = k - c*9;
                int dy = t/3 - 1, dx = t - (t/3)*3 - 1;
                int hh = h + dy, ww = px + dx;
                float v = 0.f;
                if ((unsigned)hh < H && (unsigned)ww < W)
                    v = __ldg(xb + (size_t)c*HW + hh*W + ww);
                split_bf(v, hb[jj], lb[jj]);
            }
            unsigned o = (unsigned)px*(SK*2) + (unsigned)jg*16;
            *(uint4*)(smem_c + OFF_BHI + o) = *(uint4*)hb;
            *(uint4*)(smem_c + OFF_BLO + o) = *(uint4*)lb;
        }
        __syncthreads();
        mma_chunk(smem_base, lane, wco, wpx, acc);
    }

    // epilogue: direct global stores
    int g = lane >> 2, tg = lane & 3;
    float* dst = g_t + (size_t)b*COUT*HW + (size_t)h*W;
    #pragma unroll
    for (int mt = 0; mt < 2; mt++) {
        int co0 = wco + mt*16 + g;
        int co1 = co0 + 8;
        float bv0 = (co0 < 64) ? __ldg(b_off + co0) : __ldg(b_mod + co0 - 64);
        float bv1 = (co1 < 64) ? __ldg(b_off + co1) : __ldg(b_mod + co1 - 64);
        #pragma unroll
        for (int nt = 0; nt < 8; nt++) {
            int px = wpx + nt*8 + 2*tg;
            *(float2*)(dst + (size_t)co0*HW + px) = make_float2(acc[mt][nt][0]+bv0, acc[mt][nt][1]+bv0);
            *(float2*)(dst + (size_t)co1*HW + px) = make_float2(acc[mt][nt][2]+bv1, acc[mt][nt][3]+bv1);
        }
    }
}

// ---------------- BN stats ----------------
__inline__ __device__ float warpsum(float v) {
    #pragma unroll
    for (int o = 16; o; o >>= 1) v += __shfl_down_sync(0xFFFFFFFFu, v, o);
    return v;
}

__global__ __launch_bounds__(256) void bn_stats(const float* __restrict__ gam_off,
                                                const float* __restrict__ bet_off,
                                                const float* __restrict__ gam_mod,
                                                const float* __restrict__ bet_mod) {
    int ch = blockIdx.x;
    int tid = threadIdx.x;
    float s = 0.f, s2 = 0.f;
    for (int b = 0; b < BB; b++) {
        const float4* p = (const float4*)(g_t + ((size_t)(b*2*C + ch))*HW);
        for (int i = tid; i < HW/4; i += 256) {
            float4 v = p[i];
            s  += v.x + v.y + v.z + v.w;
            s2 += v.x*v.x + v.y*v.y + v.z*v.z + v.w*v.w;
        }
    }
    __shared__ float rs[8], rs2[8];
    int lane = tid & 31, wid = tid >> 5;
    s = warpsum(s); s2 = warpsum(s2);
    if (lane == 0) { rs[wid] = s; rs2[wid] = s2; }
    __syncthreads();
    if (wid == 0) {
        s  = (lane < 8) ? rs[lane]  : 0.f;
        s2 = (lane < 8) ? rs2[lane] : 0.f;
        s = warpsum(s); s2 = warpsum(s2);
        if (lane == 0) {
            float n = (float)(BB*HW);
            float m = s / n;
            float var = s2 / n - m*m;
            float ga = (ch < 64) ? __ldg(gam_off + ch) : __ldg(gam_mod + ch - 64);
            float be = (ch < 64) ? __ldg(bet_off + ch) : __ldg(bet_mod + ch - 64);
            float sc = ga * rsqrtf(var + EPSV);
            g_scale[ch] = sc;
            g_shift[ch] = be - m * sc;
        }
    }
}

// ---------------- BN apply + SiLU ----------------
__global__ __launch_bounds__(256) void bn_act_kernel() {
    int n4 = BB*2*C*HW/4;
    for (int i = blockIdx.x*blockDim.x + threadIdx.x; i < n4; i += gridDim.x*blockDim.x) {
        int c = (i >> 12) & 127;
        float sc = g_scale[c], sh = g_shift[c];
        float4 v = ((const float4*)g_t)[i];
        v.x = v.x*sc + sh; v.y = v.y*sc + sh; v.z = v.z*sc + sh; v.w = v.w*sc + sh;
        v.x = __fdividef(v.x, 1.f + __expf(-v.x));
        v.y = __fdividef(v.y, 1.f + __expf(-v.y));
        v.z = __fdividef(v.z, 1.f + __expf(-v.z));
        v.w = __fdividef(v.w, 1.f + __expf(-v.w));
        ((float4*)g_act)[i] = v;
    }
}

// ---------------- conv2: 3 groups of 9 output channels ----------------
__global__ __launch_bounds__(256) void conv2_all(const float* __restrict__ off_w2,
                                                 const float* __restrict__ off_b2,
                                                 const float* __restrict__ mod_w2,
                                                 const float* __restrict__ mod_b2,
                                                 float* __restrict__ offs,
                                                 float* __restrict__ modu) {
    int grp = blockIdx.y;
    int g = blockIdx.x * blockDim.x + threadIdx.x;
    int b   = g >> 12;
    int rem = g & 4095;
    int h   = rem >> 5;
    int w0  = (rem & 31) * 4;
    bool sig = (grp == 2);
    int chbase = sig ? 64 : 0;
    int cobase = (grp == 1) ? 9 : 0;
    const float* wt = (sig ? mod_w2 : off_w2) + (size_t)cobase * C * 9;
    const float* bs = (sig ? mod_b2 : off_b2) + cobase;
    float* outp = sig ? (modu + (size_t)b*9*HW)
                      : (offs + ((size_t)b*18 + cobase)*HW);
    const float* ab = g_act + ((size_t)(b*2*C) + chbase)*HW;

    float acc[9][4];
    #pragma unroll
    for (int co = 0; co < 9; co++) {
        float bv = __ldg(bs + co);
        #pragma unroll
        for (int j = 0; j < 4; j++) acc[co][j] = bv;
    }

    for (int c = 0; c < C; c++) {
        const float* p = ab + (size_t)c*HW;
        float xv[3][6];
        #pragma unroll
        for (int rr = 0; rr < 3; rr++) {
            int hh = h + rr - 1;
            bool hv = (unsigned)hh < H;
            #pragma unroll
            for (int j = 0; j < 6; j++) {
                int ww = w0 + j - 1;
                xv[rr][j] = (hv && (unsigned)ww < W) ? __ldg(p + hh*W + ww) : 0.f;
            }
        }
        #pragma unroll
        for (int co = 0; co < 9; co++) {
            const float* wp = wt + ((size_t)co*C + c)*9;
            #pragma unroll
            for (int t = 0; t < 9; t++) {
                float wv = __ldg(wp + t);
                int rr = t / 3, dc = t - rr*3;
                #pragma unroll
                for (int j = 0; j < 4; j++)
                    acc[co][j] = fmaf(wv, xv[rr][dc + j], acc[co][j]);
            }
        }
    }
    #pragma unroll
    for (int co = 0; co < 9; co++) {
        float* a = acc[co];
        if (sig) {
            a[0] = __fdividef(1.f, 1.f + __expf(-a[0]));
            a[1] = __fdividef(1.f, 1.f + __expf(-a[1]));
            a[2] = __fdividef(1.f, 1.f + __expf(-a[2]));
            a[3] = __fdividef(1.f, 1.f + __expf(-a[3]));
        }
        *(float4*)(outp + (size_t)co*HW + h*W + w0) = make_float4(a[0], a[1], a[2], a[3]);
    }
}

// ---------------- deform: mma GEMM, bilinear-gather producer ----------------
__global__ __launch_bounds__(256) void deform_t(const float* __restrict__ x,
                                                const float* __restrict__ bias,
                                                float* __restrict__ out) {
    char* smem_c = smem_dyn;
    uint32_t smem_base = smem_u32(smem_c);
    int tid = threadIdx.x, wid = tid >> 5, lane = tid & 31;
    int blk = blockIdx.x;
    int b = blk >> 7, h = blk & 127;
    const float* xb = x + (size_t)b * C * HW;

    // tap tables: per (tap, px): 4 corner weights (incl. modulation) + indices
    {
        float* sWgt = (float*)(smem_c + OFF_TAPW);
        int*   sIdx = (int*)(smem_c + OFF_TAPI);
        for (int i = tid; i < 9*128; i += 256) {
            int tap = i >> 7, px = i & 127;
            size_t sp = (size_t)h*W + px;
            float offy = __ldg(g_offs + ((size_t)(b*18 + tap*2 + 1))*HW + sp);
            float offx = __ldg(g_offs + ((size_t)(b*18 + tap*2 + 0))*HW + sp);
            float m    = __ldg(g_modu + ((size_t)(b*9 + tap))*HW + sp);
            float sy = (float)h  + (float)(tap/3 - 1) + offy;
            float sx = (float)px + (float)(tap%3 - 1) + offx;
            float y0f = floorf(sy), x0f = floorf(sx);
            int y0 = (int)y0f, x0 = (int)x0f;
            float wy1 = sy - y0f, wx1 = sx - x0f;
            float wy0 = 1.f - wy1, wx0 = 1.f - wx1;
            #pragma unroll
            for (int cn = 0; cn < 4; cn++) {
                int yy = y0 + (cn >> 1);
                int xx = x0 + (cn & 1);
                float wgt = ((cn & 2) ? wy1 : wy0) * ((cn & 1) ? wx1 : wx0) * m;
                bool valid = ((unsigned)yy < H) && ((unsigned)xx < W);
                sWgt[(tap*4 + cn)*128 + px] = valid ? wgt : 0.f;
                int yc = min(max(yy, 0), H-1);
                int xc = min(max(xx, 0), W-1);
                sIdx[(tap*4 + cn)*128 + px] = yc*W + xc;
            }
        }
    }

    int wco = (wid >> 1) * 32;
    int wpx = (wid & 1) * 64;
    float acc[2][8][4];
    #pragma unroll
    for (int mt = 0; mt < 2; mt++)
        #pragma unroll
        for (int nt = 0; nt < 8; nt++)
            #pragma unroll
            for (int q = 0; q < 4; q++) acc[mt][nt][q] = 0.f;

    __syncthreads();

    for (int ck = 0; ck < NCHUNK; ck++) {
        if (ck) __syncthreads();
        {
            const uint4* sh = (const uint4*)(g_w4h + (size_t)ck*COUT*SK);
            const uint4* sl = (const uint4*)(g_w4l + (size_t)ck*COUT*SK);
            uint4* dh = (uint4*)(smem_c + OFF_AHI);
            uint4* dl = (uint4*)(smem_c + OFF_ALO);
            for (int i = tid; i < COUT*SK/8; i += 256) { dh[i] = sh[i]; dl[i] = sl[i]; }
        }
        const float* sWgt = (const float*)(smem_c + OFF_TAPW);
        const int*   sIdx = (const int*)(smem_c + OFF_TAPI);
        #pragma unroll
        for (int pass = 0; pass < 4; pass++) {
            int it = pass*256 + tid;
            int px = it >> 3, jg = it & 7;
            unsigned short hb[8], lb[8];
            #pragma unroll
            for (int jj = 0; jj < 8; jj++) {
                int k = ck*KC + jg*8 + jj;
                int c = k / 9, t = k - c*9;
                const float* xc = xb + (size_t)c*HW;
                const float* wp = sWgt + (t*4)*128 + px;
                const int*   ip = sIdx + (t*4)*128 + px;
                float v = wp[0] * __ldg(xc + ip[0]);
                v = fmaf(wp[128], __ldg(xc + ip[128]), v);
                v = fmaf(wp[256], __ldg(xc + ip[256]), v);
                v = fmaf(wp[384], __ldg(xc + ip[384]), v);
                split_bf(v, hb[jj], lb[jj]);
            }
            unsigned o = (unsigned)px*(SK*2) + (unsigned)jg*16;
            *(uint4*)(smem_c + OFF_BHI + o) = *(uint4*)hb;
            *(uint4*)(smem_c + OFF_BLO + o) = *(uint4*)lb;
        }
        __syncthreads();
        mma_chunk(smem_base, lane, wco, wpx, acc);
    }

    int g = lane >> 2, tg = lane & 3;
    float* dst = out + (size_t)b*COUT*HW + (size_t)h*W;
    #pragma unroll
    for (int mt = 0; mt < 2; mt++) {
        int co0 = wco + mt*16 + g;
        int co1 = co0 + 8;
        float bv0 = __ldg(bias + co0);
        float bv1 = __ldg(bias + co1);
        #pragma unroll
        for (int nt = 0; nt < 8; nt++) {
            int px = wpx + nt*8 + 2*tg;
            *(float2*)(dst + (size_t)co0*HW + px) = make_float2(acc[mt][nt][0]+bv0, acc[mt][nt][1]+bv0);
            *(float2*)(dst + (size_t)co1*HW + px) = make_float2(acc[mt][nt][2]+bv1, acc[mt][nt][3]+bv1);
        }
    }
}

// ---------------- launch ----------------
extern "C" void kernel_launch(void* const* d_in, const int* in_sizes, int n_in,
                              void* d_out, int out_size) {
    const float* x        = (const float*)d_in[0];
    const float* weight   = (const float*)d_in[1];
    const float* bias     = (const float*)d_in[2];
    const float* off_w1   = (const float*)d_in[3];
    const float* off_b1   = (const float*)d_in[4];
    const float* off_g    = (const float*)d_in[5];
    const float* off_be   = (const float*)d_in[6];
    const float* off_w2   = (const float*)d_in[7];
    const float* off_b2   = (const float*)d_in[8];
    const float* mod_w1   = (const float*)d_in[9];
    const float* mod_b1   = (const float*)d_in[10];
    const float* mod_g    = (const float*)d_in[11];
    const float* mod_be   = (const float*)d_in[12];
    const float* mod_w2   = (const float*)d_in[13];
    const float* mod_b2   = (const float*)d_in[14];
    float* out = (float*)d_out;

    cudaFuncSetAttribute(conv1_t, cudaFuncAttributeMaxDynamicSharedMemorySize, SMEM_GEMM);
    cudaFuncSetAttribute(deform_t, cudaFuncAttributeMaxDynamicSharedMemorySize, SMEM_DEF);

    float *offs_ptr, *modu_ptr;
    cudaGetSymbolAddress((void**)&offs_ptr, g_offs);
    cudaGetSymbolAddress((void**)&modu_ptr, g_modu);

    prep_weights<<<(NCHUNK*COUT*KC + 255)/256, 256>>>(off_w1, mod_w1, weight);
    conv1_t<<<1024, 256, SMEM_GEMM>>>(x, off_b1, mod_b1);
    bn_stats<<<128, 256>>>(off_g, off_be, mod_g, mod_be);
    bn_act_kernel<<<8192, 256>>>();
    conv2_all<<<dim3(128, 3), 256>>>(off_w2, off_b2, mod_w2, mod_b2, offs_ptr, modu_ptr);
    deform_t<<<1024, 256, SMEM_DEF>>>(x, bias, out);
}

// round 6
// speedup vs baseline: 2.2009x; 1.7621x over previous
#include <cuda_runtime.h>
#include <cuda_fp16.h>
#include <math.h>
#include <stdint.h>

#define BB 8
#define C 64
#define COUT 128
#define H 128
#define W 128
#define HW (H*W)
#define KC 64
#define NCHUNK 9
#define SK 72              // A smem k-stride (fp16 elems): 144B rows, conflict-free ldmatrix
#define SKB 136            // B smem px-stride (fp16 elems): 272B rows, conflict-free trans ldmatrix
#define EPSV 1e-5f

// ---------------- smem layout (byte offsets) ----------------
#define OFF_A   0                       // 128*72*2  = 18432
#define OFF_BHI 18432                   // 64*136*2  = 17408
#define OFF_BLO 35840                   // 17408
#define SMEM_GEMM 53248
#define OFF_TAPW 53248                  // deform: float [36][128] = 18432
#define OFF_TAPI (53248 + 18432)        // deform: int   [36][128] = 18432
#define SMEM_DEF  (OFF_TAPI + 18432)    // 90112

// ---------------- device scratch ----------------
__device__ float g_t[BB*2*C*HW];
__device__ float g_act[BB*2*C*HW];
__device__ float g_offs[BB*18*HW];
__device__ float g_modu[BB*9*HW];
__device__ float g_scale[2*C];
__device__ float g_shift[2*C];
// per-chunk weight tiles [NCHUNK][128 co][SK] fp16 (k pad 64..71 unread)
__device__ __align__(16) unsigned short g_w1[NCHUNK*COUT*SK];
__device__ __align__(16) unsigned short g_w4[NCHUNK*COUT*SK];

// ---------------- helpers ----------------
__device__ __forceinline__ uint32_t smem_u32(const void* p) {
    uint32_t a;
    asm("{ .reg .u64 t; cvta.to.shared.u64 t, %1; cvt.u32.u64 %0, t; }" : "=r"(a) : "l"(p));
    return a;
}
__device__ __forceinline__ void split_h(float v, unsigned short& hb, unsigned short& lb) {
    __half h = __float2half_rn(v);
    __half l = __float2half_rn(v - __half2float(h));
    hb = *reinterpret_cast<unsigned short*>(&h);
    lb = *reinterpret_cast<unsigned short*>(&l);
}
__device__ __forceinline__ void ldsm_x4(uint32_t a[4], uint32_t addr) {
    asm volatile("ldmatrix.sync.aligned.m8n8.x4.shared.b16 {%0,%1,%2,%3}, [%4];"
        : "=r"(a[0]), "=r"(a[1]), "=r"(a[2]), "=r"(a[3]) : "r"(addr));
}
__device__ __forceinline__ void ldsm_x2_t(uint32_t b[2], uint32_t addr) {
    asm volatile("ldmatrix.sync.aligned.m8n8.x2.trans.shared.b16 {%0,%1}, [%2];"
        : "=r"(b[0]), "=r"(b[1]) : "r"(addr));
}
__device__ __forceinline__ void mma_f16(float d[4], const uint32_t a[4], const uint32_t b[2]) {
    asm volatile("mma.sync.aligned.m16n8k16.row.col.f32.f16.f16.f32 "
        "{%0,%1,%2,%3}, {%4,%5,%6,%7}, {%8,%9}, {%0,%1,%2,%3};"
        : "+f"(d[0]), "+f"(d[1]), "+f"(d[2]), "+f"(d[3])
        : "r"(a[0]), "r"(a[1]), "r"(a[2]), "r"(a[3]), "r"(b[0]), "r"(b[1]));
}
// A (row-major [co][SK]) ldmatrix address
__device__ __forceinline__ uint32_t a_addr(uint32_t base, int row0, int k0, int lane) {
    int q = lane >> 3;
    int row = row0 + (lane & 7) + (q & 1) * 8;
    int col = k0 + (q >> 1) * 8;
    return base + (uint32_t)(row * SK + col) * 2u;
}
// B (k-major [k][SKB]) trans ldmatrix address: lanes 0-15 -> k rows k0..k0+15 at col n0
__device__ __forceinline__ uint32_t b_addr_t(uint32_t base, int k0, int n0, int lane) {
    int row = k0 + (lane & 15);
    return base + (uint32_t)(row * SKB + n0) * 2u;
}

// ---------------- weight prep ----------------
__global__ void prep_weights(const float* __restrict__ off_w1,
                             const float* __restrict__ mod_w1,
                             const float* __restrict__ wmain) {
    int i = blockIdx.x * 256 + threadIdx.x;
    if (i >= NCHUNK*COUT*KC) return;
    int ck = i / (COUT*KC);
    int r  = i - ck*(COUT*KC);
    int co = r >> 6;
    int j  = r & 63;
    int k = ck*KC + j;
    int c = k / 9, t = k - c*9;
    size_t soff = (size_t)(ck*COUT + co)*SK + j;
    float w1 = (co < 64) ? off_w1[(co*C + c)*9 + t] : mod_w1[((co-64)*C + c)*9 + t];
    __half hv = __float2half_rn(w1);
    g_w1[soff] = *reinterpret_cast<unsigned short*>(&hv);
    float w4 = wmain[(co*C + c)*9 + t];
    hv = __float2half_rn(w4);
    g_w4[soff] = *reinterpret_cast<unsigned short*>(&hv);
}

extern __shared__ char smem_dyn[];

// ---------------- shared GEMM consumer: one KC-chunk (2 mma terms) ----------
__device__ __forceinline__ void mma_chunk(uint32_t smem_base, int lane, int wco, int wpx,
                                          float acc[2][8][4]) {
    uint32_t baseA  = smem_base + OFF_A;
    uint32_t baseBh = smem_base + OFF_BHI;
    uint32_t baseBl = smem_base + OFF_BLO;
    #pragma unroll
    for (int ks = 0; ks < 4; ks++) {
        int k0 = ks * 16;
        uint32_t a[2][4];
        #pragma unroll
        for (int mt = 0; mt < 2; mt++)
            ldsm_x4(a[mt], a_addr(baseA, wco + mt*16, k0, lane));
        #pragma unroll
        for (int nt = 0; nt < 8; nt++) {
            uint32_t bh[2], bl[2];
            ldsm_x2_t(bh, b_addr_t(baseBh, k0, wpx + nt*8, lane));
            ldsm_x2_t(bl, b_addr_t(baseBl, k0, wpx + nt*8, lane));
            #pragma unroll
            for (int mt = 0; mt < 2; mt++) {
                mma_f16(acc[mt][nt], a[mt], bh);
                mma_f16(acc[mt][nt], a[mt], bl);
            }
        }
    }
}

// ---------------- conv1: mma GEMM, coalesced im2col producer ----------------
__global__ __launch_bounds__(256) void conv1_t(const float* __restrict__ x,
                                               const float* __restrict__ b_off,
                                               const float* __restrict__ b_mod) {
    char* smem_c = smem_dyn;
    uint32_t smem_base = smem_u32(smem_c);
    int tid = threadIdx.x, wid = tid >> 5, lane = tid & 31;
    int blk = blockIdx.x;
    int b = blk >> 7, h = blk & 127;
    const float* xb = x + (size_t)b * C * HW;

    int wco = (wid >> 1) * 32;
    int wpx = (wid & 1) * 64;
    float acc[2][8][4];
    #pragma unroll
    for (int mt = 0; mt < 2; mt++)
        #pragma unroll
        for (int nt = 0; nt < 8; nt++)
            #pragma unroll
            for (int q = 0; q < 4; q++) acc[mt][nt][q] = 0.f;

    int px = tid & 127, kh = tid >> 7;

    for (int ck = 0; ck < NCHUNK; ck++) {
        if (ck) __syncthreads();
        // A tile copy (fp16 weights, 18432 B)
        {
            const uint4* sa = (const uint4*)(g_w1 + (size_t)ck*COUT*SK);
            uint4* da = (uint4*)(smem_c + OFF_A);
            for (int i = tid; i < COUT*SK/8; i += 256) da[i] = sa[i];
        }
        // B tile: k-major im2col + fp16 split; coalesced over px
        #pragma unroll 4
        for (int kk2 = 0; kk2 < 32; kk2++) {
            int kk = kh*32 + kk2;
            int k = ck*KC + kk;
            int c = k / 9, t = k - c*9;
            int hh = h + t/3 - 1, ww = px + (t - (t/3)*3) - 1;
            float v = 0.f;
            if ((unsigned)hh < H && (unsigned)ww < W)
                v = __ldg(xb + (size_t)c*HW + hh*W + ww);
            unsigned short hb, lb;
            split_h(v, hb, lb);
            *(unsigned short*)(smem_c + OFF_BHI + kk*(SKB*2) + px*2) = hb;
            *(unsigned short*)(smem_c + OFF_BLO + kk*(SKB*2) + px*2) = lb;
        }
        __syncthreads();
        mma_chunk(smem_base, lane, wco, wpx, acc);
    }

    // epilogue: direct global stores
    int g = lane >> 2, tg = lane & 3;
    float* dst = g_t + (size_t)b*COUT*HW + (size_t)h*W;
    #pragma unroll
    for (int mt = 0; mt < 2; mt++) {
        int co0 = wco + mt*16 + g;
        int co1 = co0 + 8;
        float bv0 = (co0 < 64) ? __ldg(b_off + co0) : __ldg(b_mod + co0 - 64);
        float bv1 = (co1 < 64) ? __ldg(b_off + co1) : __ldg(b_mod + co1 - 64);
        #pragma unroll
        for (int nt = 0; nt < 8; nt++) {
            int p2 = wpx + nt*8 + 2*tg;
            *(float2*)(dst + (size_t)co0*HW + p2) = make_float2(acc[mt][nt][0]+bv0, acc[mt][nt][1]+bv0);
            *(float2*)(dst + (size_t)co1*HW + p2) = make_float2(acc[mt][nt][2]+bv1, acc[mt][nt][3]+bv1);
        }
    }
}

// ---------------- BN stats ----------------
__inline__ __device__ float warpsum(float v) {
    #pragma unroll
    for (int o = 16; o; o >>= 1) v += __shfl_down_sync(0xFFFFFFFFu, v, o);
    return v;
}

__global__ __launch_bounds__(256) void bn_stats(const float* __restrict__ gam_off,
                                                const float* __restrict__ bet_off,
                                                const float* __restrict__ gam_mod,
                                                const float* __restrict__ bet_mod) {
    int ch = blockIdx.x;
    int tid = threadIdx.x;
    float s = 0.f, s2 = 0.f;
    for (int b = 0; b < BB; b++) {
        const float4* p = (const float4*)(g_t + ((size_t)(b*2*C + ch))*HW);
        for (int i = tid; i < HW/4; i += 256) {
            float4 v = p[i];
            s  += v.x + v.y + v.z + v.w;
            s2 += v.x*v.x + v.y*v.y + v.z*v.z + v.w*v.w;
        }
    }
    __shared__ float rs[8], rs2[8];
    int lane = tid & 31, wid = tid >> 5;
    s = warpsum(s); s2 = warpsum(s2);
    if (lane == 0) { rs[wid] = s; rs2[wid] = s2; }
    __syncthreads();
    if (wid == 0) {
        s  = (lane < 8) ? rs[lane]  : 0.f;
        s2 = (lane < 8) ? rs2[lane] : 0.f;
        s = warpsum(s); s2 = warpsum(s2);
        if (lane == 0) {
            float n = (float)(BB*HW);
            float m = s / n;
            float var = s2 / n - m*m;
            float ga = (ch < 64) ? __ldg(gam_off + ch) : __ldg(gam_mod + ch - 64);
            float be = (ch < 64) ? __ldg(bet_off + ch) : __ldg(bet_mod + ch - 64);
            float sc = ga * rsqrtf(var + EPSV);
            g_scale[ch] = sc;
            g_shift[ch] = be - m * sc;
        }
    }
}

// ---------------- BN apply + SiLU ----------------
__global__ __launch_bounds__(256) void bn_act_kernel() {
    int n4 = BB*2*C*HW/4;
    for (int i = blockIdx.x*blockDim.x + threadIdx.x; i < n4; i += gridDim.x*blockDim.x) {
        int c = (i >> 12) & 127;
        float sc = g_scale[c], sh = g_shift[c];
        float4 v = ((const float4*)g_t)[i];
        v.x = v.x*sc + sh; v.y = v.y*sc + sh; v.z = v.z*sc + sh; v.w = v.w*sc + sh;
        v.x = __fdividef(v.x, 1.f + __expf(-v.x));
        v.y = __fdividef(v.y, 1.f + __expf(-v.y));
        v.z = __fdividef(v.z, 1.f + __expf(-v.z));
        v.w = __fdividef(v.w, 1.f + __expf(-v.w));
        ((float4*)g_act)[i] = v;
    }
}

// ---------------- conv2: smem-staged, 3 groups of 9 output channels ---------
__global__ __launch_bounds__(256) void conv2_all(const float* __restrict__ off_w2,
                                                 const float* __restrict__ off_b2,
                                                 const float* __restrict__ mod_w2,
                                                 const float* __restrict__ mod_b2,
                                                 float* __restrict__ offs,
                                                 float* __restrict__ modu) {
    __shared__ float sx[10][132];
    int grp = blockIdx.y;
    int tid = threadIdx.x;
    int b  = blockIdx.x >> 4;
    int h0 = (blockIdx.x & 15) * 8;
    int h  = h0 + (tid >> 5);
    int w0 = (tid & 31) * 4;

    bool sig = (grp == 2);
    int chbase = sig ? 64 : 0;
    int cobase = (grp == 1) ? 9 : 0;
    const float* wt = (sig ? mod_w2 : off_w2) + (size_t)cobase * C * 9;
    const float* bs = (sig ? mod_b2 : off_b2) + cobase;
    float* outp = sig ? (modu + (size_t)b*9*HW)
                      : (offs + ((size_t)b*18 + cobase)*HW);
    const float* ab = g_act + ((size_t)(b*2*C) + chbase)*HW;

    // zero halo columns once (loader never touches cols 0 and 129)
    if (tid < 10) { sx[tid][0] = 0.f; sx[tid][129] = 0.f; }

    float acc[9][4];
    #pragma unroll
    for (int co = 0; co < 9; co++) {
        float bv = __ldg(bs + co);
        #pragma unroll
        for (int j = 0; j < 4; j++) acc[co][j] = bv;
    }

    int rbase = tid >> 5;
    for (int c = 0; c < C; c++) {
        __syncthreads();
        const float* p = ab + (size_t)c*HW;
        for (int i = tid; i < 1280; i += 256) {
            int r = i >> 7, col = i & 127;
            int hh = h0 - 1 + r;
            sx[r][1 + col] = ((unsigned)hh < H) ? __ldg(p + hh*W + col) : 0.f;
        }
        __syncthreads();

        float xv[3][6];
        #pragma unroll
        for (int rr = 0; rr < 3; rr++) {
            float4 va = *(const float4*)&sx[rbase + rr][w0];
            float4 vb = *(const float4*)&sx[rbase + rr][w0 + 4];
            xv[rr][0] = va.x; xv[rr][1] = va.y; xv[rr][2] = va.z;
            xv[rr][3] = va.w; xv[rr][4] = vb.x; xv[rr][5] = vb.y;
        }
        #pragma unroll
        for (int co = 0; co < 9; co++) {
            const float* wp = wt + ((size_t)co*C + c)*9;
            #pragma unroll
            for (int t = 0; t < 9; t++) {
                float wv = __ldg(wp + t);
                int rr = t / 3, dc = t - rr*3;
                #pragma unroll
                for (int j = 0; j < 4; j++)
                    acc[co][j] = fmaf(wv, xv[rr][dc + j], acc[co][j]);
            }
        }
    }
    #pragma unroll
    for (int co = 0; co < 9; co++) {
        float* a = acc[co];
        if (sig) {
            a[0] = __fdividef(1.f, 1.f + __expf(-a[0]));
            a[1] = __fdividef(1.f, 1.f + __expf(-a[1]));
            a[2] = __fdividef(1.f, 1.f + __expf(-a[2]));
            a[3] = __fdividef(1.f, 1.f + __expf(-a[3]));
        }
        *(float4*)(outp + (size_t)co*HW + h*W + w0) = make_float4(a[0], a[1], a[2], a[3]);
    }
}

// ---------------- deform: mma GEMM, coalesced bilinear-gather producer ------
__global__ __launch_bounds__(256) void deform_t(const float* __restrict__ x,
                                                const float* __restrict__ bias,
                                                float* __restrict__ out) {
    char* smem_c = smem_dyn;
    uint32_t smem_base = smem_u32(smem_c);
    int tid = threadIdx.x, wid = tid >> 5, lane = tid & 31;
    int blk = blockIdx.x;
    int b = blk >> 7, h = blk & 127;
    const float* xb = x + (size_t)b * C * HW;

    // tap tables: per (tap, px): 4 corner weights (incl. modulation) + indices
    {
        float* sWgt = (float*)(smem_c + OFF_TAPW);
        int*   sIdx = (int*)(smem_c + OFF_TAPI);
        for (int i = tid; i < 9*128; i += 256) {
            int tap = i >> 7, px = i & 127;
            size_t sp = (size_t)h*W + px;
            float offy = __ldg(g_offs + ((size_t)(b*18 + tap*2 + 1))*HW + sp);
            float offx = __ldg(g_offs + ((size_t)(b*18 + tap*2 + 0))*HW + sp);
            float m    = __ldg(g_modu + ((size_t)(b*9 + tap))*HW + sp);
            float sy = (float)h  + (float)(tap/3 - 1) + offy;
            float sx2 = (float)px + (float)(tap%3 - 1) + offx;
            float y0f = floorf(sy), x0f = floorf(sx2);
            int y0 = (int)y0f, x0 = (int)x0f;
            float wy1 = sy - y0f, wx1 = sx2 - x0f;
            float wy0 = 1.f - wy1, wx0 = 1.f - wx1;
            #pragma unroll
            for (int cn = 0; cn < 4; cn++) {
                int yy = y0 + (cn >> 1);
                int xx = x0 + (cn & 1);
                float wgt = ((cn & 2) ? wy1 : wy0) * ((cn & 1) ? wx1 : wx0) * m;
                bool valid = ((unsigned)yy < H) && ((unsigned)xx < W);
                sWgt[(tap*4 + cn)*128 + px] = valid ? wgt : 0.f;
                int yc = min(max(yy, 0), H-1);
                int xc = min(max(xx, 0), W-1);
                sIdx[(tap*4 + cn)*128 + px] = yc*W + xc;
            }
        }
    }

    int wco = (wid >> 1) * 32;
    int wpx = (wid & 1) * 64;
    float acc[2][8][4];
    #pragma unroll
    for (int mt = 0; mt < 2; mt++)
        #pragma unroll
        for (int nt = 0; nt < 8; nt++)
            #pragma unroll
            for (int q = 0; q < 4; q++) acc[mt][nt][q] = 0.f;

    int px = tid & 127, kh = tid >> 7;
    const float* sWgt = (const float*)(smem_c + OFF_TAPW);
    const int*   sIdx = (const int*)(smem_c + OFF_TAPI);
    __syncthreads();

    for (int ck = 0; ck < NCHUNK; ck++) {
        if (ck) __syncthreads();
        {
            const uint4* sa = (const uint4*)(g_w4 + (size_t)ck*COUT*SK);
            uint4* da = (uint4*)(smem_c + OFF_A);
            for (int i = tid; i < COUT*SK/8; i += 256) da[i] = sa[i];
        }
        #pragma unroll 4
        for (int kk2 = 0; kk2 < 32; kk2++) {
            int kk = kh*32 + kk2;
            int k = ck*KC + kk;
            int c = k / 9, t = k - c*9;
            const float* xc = xb + (size_t)c*HW;
            const float* wp = sWgt + (t*4)*128 + px;
            const int*   ip = sIdx + (t*4)*128 + px;
            float v = wp[0] * __ldg(xc + ip[0]);
            v = fmaf(wp[128], __ldg(xc + ip[128]), v);
            v = fmaf(wp[256], __ldg(xc + ip[256]), v);
            v = fmaf(wp[384], __ldg(xc + ip[384]), v);
            unsigned short hb, lb;
            split_h(v, hb, lb);
            *(unsigned short*)(smem_c + OFF_BHI + kk*(SKB*2) + px*2) = hb;
            *(unsigned short*)(smem_c + OFF_BLO + kk*(SKB*2) + px*2) = lb;
        }
        __syncthreads();
        mma_chunk(smem_base, lane, wco, wpx, acc);
    }

    int g = lane >> 2, tg = lane & 3;
    float* dst = out + (size_t)b*COUT*HW + (size_t)h*W;
    #pragma unroll
    for (int mt = 0; mt < 2; mt++) {
        int co0 = wco + mt*16 + g;
        int co1 = co0 + 8;
        float bv0 = __ldg(bias + co0);
        float bv1 = __ldg(bias + co1);
        #pragma unroll
        for (int nt = 0; nt < 8; nt++) {
            int p2 = wpx + nt*8 + 2*tg;
            *(float2*)(dst + (size_t)co0*HW + p2) = make_float2(acc[mt][nt][0]+bv0, acc[mt][nt][1]+bv0);
            *(float2*)(dst + (size_t)co1*HW + p2) = make_float2(acc[mt][nt][2]+bv1, acc[mt][nt][3]+bv1);
        }
    }
}

// ---------------- launch ----------------
extern "C" void kernel_launch(void* const* d_in, const int* in_sizes, int n_in,
                              void* d_out, int out_size) {
    const float* x        = (const float*)d_in[0];
    const float* weight   = (const float*)d_in[1];
    const float* bias     = (const float*)d_in[2];
    const float* off_w1   = (const float*)d_in[3];
    const float* off_b1   = (const float*)d_in[4];
    const float* off_g    = (const float*)d_in[5];
    const float* off_be   = (const float*)d_in[6];
    const float* off_w2   = (const float*)d_in[7];
    const float* off_b2   = (const float*)d_in[8];
    const float* mod_w1   = (const float*)d_in[9];
    const float* mod_b1   = (const float*)d_in[10];
    const float* mod_g    = (const float*)d_in[11];
    const float* mod_be   = (const float*)d_in[12];
    const float* mod_w2   = (const float*)d_in[13];
    const float* mod_b2   = (const float*)d_in[14];
    float* out = (float*)d_out;

    cudaFuncSetAttribute(conv1_t, cudaFuncAttributeMaxDynamicSharedMemorySize, SMEM_GEMM);
    cudaFuncSetAttribute(deform_t, cudaFuncAttributeMaxDynamicSharedMemorySize, SMEM_DEF);

    float *offs_ptr, *modu_ptr;
    cudaGetSymbolAddress((void**)&offs_ptr, g_offs);
    cudaGetSymbolAddress((void**)&modu_ptr, g_modu);

    prep_weights<<<(NCHUNK*COUT*KC + 255)/256, 256>>>(off_w1, mod_w1, weight);
    conv1_t<<<1024, 256, SMEM_GEMM>>>(x, off_b1, mod_b1);
    bn_stats<<<128, 256>>>(off_g, off_be, mod_g, mod_be);
    bn_act_kernel<<<8192, 256>>>();
    conv2_all<<<dim3(128, 3), 256>>>(off_w2, off_b2, mod_w2, mod_b2, offs_ptr, modu_ptr);
    deform_t<<<1024, 256, SMEM_DEF>>>(x, bias, out);
}

// round 7
// speedup vs baseline: 2.9911x; 1.3591x over previous
#include <cuda_runtime.h>
#include <cuda_fp16.h>
#include <math.h>
#include <stdint.h>

#define BB 8
#define C 64
#define COUT 128
#define H 128
#define W 128
#define HW (H*W)
#define KC 64
#define NCHUNK 9
#define SK 72              // A smem k-stride (fp16): 144B rows, conflict-free ldmatrix
#define SKB 136            // B smem px-stride (fp16): 272B rows, conflict-free trans ldmatrix
#define EPSV 1e-5f

// ---------------- smem layout (byte offsets) ----------------
#define OFF_A   0                       // 128*72*2  = 18432
#define OFF_B   18432                   // 64*136*2  = 17408
#define OFF_STG 35840                   // conv1: float [8][3][132] = 12672
#define SMEM_C1 (35840 + 12672)         // 48512
#define OFF_TAP 35840                   // deform: float2 [36][128] = 36864
#define SMEM_DEF (35840 + 36864)        // 72704

// ---------------- device scratch ----------------
__device__ float g_t[BB*2*C*HW];
__device__ float g_offs[BB*18*HW];
__device__ float g_modu[BB*9*HW];
__device__ float g_scale[2*C];
__device__ float g_shift[2*C];
// per-chunk weight tiles [NCHUNK][128 co][SK] fp16 (k pad 64..71 unread)
__device__ __align__(16) unsigned short g_w1[NCHUNK*COUT*SK];
__device__ __align__(16) unsigned short g_w4[NCHUNK*COUT*SK];

// ---------------- helpers ----------------
__device__ __forceinline__ uint32_t smem_u32(const void* p) {
    uint32_t a;
    asm("{ .reg .u64 t; cvta.to.shared.u64 t, %1; cvt.u32.u64 %0, t; }" : "=r"(a) : "l"(p));
    return a;
}
__device__ __forceinline__ unsigned short h_bits(float v) {
    __half h = __float2half_rn(v);
    return *reinterpret_cast<unsigned short*>(&h);
}
__device__ __forceinline__ void ldsm_x4(uint32_t a[4], uint32_t addr) {
    asm volatile("ldmatrix.sync.aligned.m8n8.x4.shared.b16 {%0,%1,%2,%3}, [%4];"
        : "=r"(a[0]), "=r"(a[1]), "=r"(a[2]), "=r"(a[3]) : "r"(addr));
}
__device__ __forceinline__ void ldsm_x2_t(uint32_t b[2], uint32_t addr) {
    asm volatile("ldmatrix.sync.aligned.m8n8.x2.trans.shared.b16 {%0,%1}, [%2];"
        : "=r"(b[0]), "=r"(b[1]) : "r"(addr));
}
__device__ __forceinline__ void mma_f16(float d[4], const uint32_t a[4], const uint32_t b[2]) {
    asm volatile("mma.sync.aligned.m16n8k16.row.col.f32.f16.f16.f32 "
        "{%0,%1,%2,%3}, {%4,%5,%6,%7}, {%8,%9}, {%0,%1,%2,%3};"
        : "+f"(d[0]), "+f"(d[1]), "+f"(d[2]), "+f"(d[3])
        : "r"(a[0]), "r"(a[1]), "r"(a[2]), "r"(a[3]), "r"(b[0]), "r"(b[1]));
}
__device__ __forceinline__ uint32_t a_addr(uint32_t base, int row0, int k0, int lane) {
    int q = lane >> 3;
    int row = row0 + (lane & 7) + (q & 1) * 8;
    int col = k0 + (q >> 1) * 8;
    return base + (uint32_t)(row * SK + col) * 2u;
}
__device__ __forceinline__ uint32_t b_addr_t(uint32_t base, int k0, int n0, int lane) {
    int row = k0 + (lane & 15);
    return base + (uint32_t)(row * SKB + n0) * 2u;
}

// ---------------- weight prep ----------------
__global__ void prep_weights(const float* __restrict__ off_w1,
                             const float* __restrict__ mod_w1,
                             const float* __restrict__ wmain) {
    int i = blockIdx.x * 256 + threadIdx.x;
    if (i >= NCHUNK*COUT*KC) return;
    int ck = i / (COUT*KC);
    int r  = i - ck*(COUT*KC);
    int co = r >> 6;
    int j  = r & 63;
    int k = ck*KC + j;
    int c = k / 9, t = k - c*9;
    size_t soff = (size_t)(ck*COUT + co)*SK + j;
    float w1 = (co < 64) ? off_w1[(co*C + c)*9 + t] : mod_w1[((co-64)*C + c)*9 + t];
    g_w1[soff] = h_bits(w1);
    g_w4[soff] = h_bits(wmain[(co*C + c)*9 + t]);
}

extern __shared__ char smem_dyn[];

// ---------------- shared GEMM consumer: one KC-chunk (single B term) --------
__device__ __forceinline__ void mma_chunk(uint32_t smem_base, int lane, int wco, int wpx,
                                          float acc[2][8][4]) {
    uint32_t baseA = smem_base + OFF_A;
    uint32_t baseB = smem_base + OFF_B;
    #pragma unroll
    for (int ks = 0; ks < 4; ks++) {
        int k0 = ks * 16;
        uint32_t a[2][4];
        #pragma unroll
        for (int mt = 0; mt < 2; mt++)
            ldsm_x4(a[mt], a_addr(baseA, wco + mt*16, k0, lane));
        #pragma unroll
        for (int nt = 0; nt < 8; nt++) {
            uint32_t bh[2];
            ldsm_x2_t(bh, b_addr_t(baseB, k0, wpx + nt*8, lane));
            #pragma unroll
            for (int mt = 0; mt < 2; mt++)
                mma_f16(acc[mt][nt], a[mt], bh);
        }
    }
}

// ---------------- conv1: mma GEMM, smem-staged im2col producer --------------
__global__ __launch_bounds__(256) void conv1_t(const float* __restrict__ x,
                                               const float* __restrict__ b_off,
                                               const float* __restrict__ b_mod) {
    char* smem_c = smem_dyn;
    uint32_t smem_base = smem_u32(smem_c);
    int tid = threadIdx.x, wid = tid >> 5, lane = tid & 31;
    int blk = blockIdx.x;
    int b = blk >> 7, h = blk & 127;
    const float* xb = x + (size_t)b * C * HW;
    float* stg = (float*)(smem_c + OFF_STG);

    int wco = (wid >> 1) * 32;
    int wpx = (wid & 1) * 64;
    float acc[2][8][4];
    #pragma unroll
    for (int mt = 0; mt < 2; mt++)
        #pragma unroll
        for (int nt = 0; nt < 8; nt++)
            #pragma unroll
            for (int q = 0; q < 4; q++) acc[mt][nt][q] = 0.f;

    int px = tid & 127, kh = tid >> 7;

    // halo columns zero (cols 0 and 129 of each of the 24 stage rows)
    if (tid < 48) stg[(tid >> 1)*132 + ((tid & 1) ? 129 : 0)] = 0.f;

    for (int ck = 0; ck < NCHUNK; ck++) {
        if (ck) __syncthreads();
        // A tile copy (fp16 weights, 18432 B)
        {
            const uint4* sa = (const uint4*)(g_w1 + (size_t)ck*COUT*SK);
            uint4* da = (uint4*)(smem_c + OFF_A);
            for (int i = tid; i < COUT*SK/8; i += 256) da[i] = sa[i];
        }
        // stage fill: 8 channels x 3 rows x 128 cols, coalesced
        int c_lo = (ck*KC) / 9;
        #pragma unroll
        for (int it = 0; it < 12; it++) {
            int i = it*256 + tid;
            int ch = i / 384;
            int rr = (i - ch*384) >> 7;
            int col = i & 127;
            int hh = h + rr - 1;
            float v = ((unsigned)hh < H) ? __ldg(xb + (size_t)(c_lo + ch)*HW + hh*W + col) : 0.f;
            stg[(ch*3 + rr)*132 + 1 + col] = v;
        }
        __syncthreads();
        // B build from stage (1 LDS + 1 STS per k)
        {
            int k0h = ck*KC + kh*32;
            int c = k0h / 9, t = k0h - 9*c;
            #pragma unroll 8
            for (int kk2 = 0; kk2 < 32; kk2++) {
                int dy = t / 3, dxm = t - dy*3;
                float v = stg[((c - c_lo)*3 + dy)*132 + px + dxm];
                *(unsigned short*)(smem_c + OFF_B + (kh*32 + kk2)*(SKB*2) + px*2) = h_bits(v);
                if (++t == 9) { t = 0; c++; }
            }
        }
        __syncthreads();
        mma_chunk(smem_base, lane, wco, wpx, acc);
    }

    // epilogue
    int g = lane >> 2, tg = lane & 3;
    float* dst = g_t + (size_t)b*COUT*HW + (size_t)h*W;
    #pragma unroll
    for (int mt = 0; mt < 2; mt++) {
        int co0 = wco + mt*16 + g;
        int co1 = co0 + 8;
        float bv0 = (co0 < 64) ? __ldg(b_off + co0) : __ldg(b_mod + co0 - 64);
        float bv1 = (co1 < 64) ? __ldg(b_off + co1) : __ldg(b_mod + co1 - 64);
        #pragma unroll
        for (int nt = 0; nt < 8; nt++) {
            int p2 = wpx + nt*8 + 2*tg;
            *(float2*)(dst + (size_t)co0*HW + p2) = make_float2(acc[mt][nt][0]+bv0, acc[mt][nt][1]+bv0);
            *(float2*)(dst + (size_t)co1*HW + p2) = make_float2(acc[mt][nt][2]+bv1, acc[mt][nt][3]+bv1);
        }
    }
}

// ---------------- BN stats ----------------
__inline__ __device__ float warpsum(float v) {
    #pragma unroll
    for (int o = 16; o; o >>= 1) v += __shfl_down_sync(0xFFFFFFFFu, v, o);
    return v;
}

__global__ __launch_bounds__(256) void bn_stats(const float* __restrict__ gam_off,
                                                const float* __restrict__ bet_off,
                                                const float* __restrict__ gam_mod,
                                                const float* __restrict__ bet_mod) {
    int ch = blockIdx.x;
    int tid = threadIdx.x;
    float s = 0.f, s2 = 0.f;
    for (int b = 0; b < BB; b++) {
        const float4* p = (const float4*)(g_t + ((size_t)(b*2*C + ch))*HW);
        for (int i = tid; i < HW/4; i += 256) {
            float4 v = p[i];
            s  += v.x + v.y + v.z + v.w;
            s2 += v.x*v.x + v.y*v.y + v.z*v.z + v.w*v.w;
        }
    }
    __shared__ float rs[8], rs2[8];
    int lane = tid & 31, wid = tid >> 5;
    s = warpsum(s); s2 = warpsum(s2);
    if (lane == 0) { rs[wid] = s; rs2[wid] = s2; }
    __syncthreads();
    if (wid == 0) {
        s  = (lane < 8) ? rs[lane]  : 0.f;
        s2 = (lane < 8) ? rs2[lane] : 0.f;
        s = warpsum(s); s2 = warpsum(s2);
        if (lane == 0) {
            float n = (float)(BB*HW);
            float m = s / n;
            float var = s2 / n - m*m;
            float ga = (ch < 64) ? __ldg(gam_off + ch) : __ldg(gam_mod + ch - 64);
            float be = (ch < 64) ? __ldg(bet_off + ch) : __ldg(bet_mod + ch - 64);
            float sc = ga * rsqrtf(var + EPSV);
            g_scale[ch] = sc;
            g_shift[ch] = be - m * sc;
        }
    }
}

// ---------------- conv2: fused BN+SiLU on load, smem-staged -----------------
__global__ __launch_bounds__(256) void conv2_all(const float* __restrict__ off_w2,
                                                 const float* __restrict__ off_b2,
                                                 const float* __restrict__ mod_w2,
                                                 const float* __restrict__ mod_b2,
                                                 float* __restrict__ offs,
                                                 float* __restrict__ modu) {
    __shared__ float sx[10][132];
    int grp = blockIdx.y;
    int tid = threadIdx.x;
    int b  = blockIdx.x >> 4;
    int h0 = (blockIdx.x & 15) * 8;
    int h  = h0 + (tid >> 5);
    int w0 = (tid & 31) * 4;

    bool sig = (grp == 2);
    int chbase = sig ? 64 : 0;
    int cobase = (grp == 1) ? 9 : 0;
    const float* wt = (sig ? mod_w2 : off_w2) + (size_t)cobase * C * 9;
    const float* bs = (sig ? mod_b2 : off_b2) + cobase;
    float* outp = sig ? (modu + (size_t)b*9*HW)
                      : (offs + ((size_t)b*18 + cobase)*HW);
    const float* tb = g_t + ((size_t)(b*COUT) + chbase)*HW;

    if (tid < 10) { sx[tid][0] = 0.f; sx[tid][129] = 0.f; }

    float acc[9][4];
    #pragma unroll
    for (int co = 0; co < 9; co++) {
        float bv = __ldg(bs + co);
        #pragma unroll
        for (int j = 0; j < 4; j++) acc[co][j] = bv;
    }

    int rbase = tid >> 5;
    for (int c = 0; c < C; c++) {
        float scv = g_scale[chbase + c];
        float shv = g_shift[chbase + c];
        __syncthreads();
        const float* p = tb + (size_t)c*HW;
        for (int i = tid; i < 1280; i += 256) {
            int r = i >> 7, col = i & 127;
            int hh = h0 - 1 + r;
            float v = 0.f;
            if ((unsigned)hh < H) {
                float raw = __ldg(p + hh*W + col) * scv + shv;
                v = __fdividef(raw, 1.f + __expf(-raw));
            }
            sx[r][1 + col] = v;
        }
        __syncthreads();

        float xv[3][6];
        #pragma unroll
        for (int rr = 0; rr < 3; rr++) {
            float4 va = *(const float4*)&sx[rbase + rr][w0];
            float4 vb = *(const float4*)&sx[rbase + rr][w0 + 4];
            xv[rr][0] = va.x; xv[rr][1] = va.y; xv[rr][2] = va.z;
            xv[rr][3] = va.w; xv[rr][4] = vb.x; xv[rr][5] = vb.y;
        }
        #pragma unroll
        for (int co = 0; co < 9; co++) {
            const float* wp = wt + ((size_t)co*C + c)*9;
            #pragma unroll
            for (int t = 0; t < 9; t++) {
                float wv = __ldg(wp + t);
                int rr = t / 3, dc = t - rr*3;
                #pragma unroll
                for (int j = 0; j < 4; j++)
                    acc[co][j] = fmaf(wv, xv[rr][dc + j], acc[co][j]);
            }
        }
    }
    #pragma unroll
    for (int co = 0; co < 9; co++) {
        float* a = acc[co];
        if (sig) {
            a[0] = __fdividef(1.f, 1.f + __expf(-a[0]));
            a[1] = __fdividef(1.f, 1.f + __expf(-a[1]));
            a[2] = __fdividef(1.f, 1.f + __expf(-a[2]));
            a[3] = __fdividef(1.f, 1.f + __expf(-a[3]));
        }
        *(float4*)(outp + (size_t)co*HW + h*W + w0) = make_float4(a[0], a[1], a[2], a[3]);
    }
}

// ---------------- deform: mma GEMM, tap-outer gather producer ---------------
__global__ __launch_bounds__(256) void deform_t(const float* __restrict__ x,
                                                const float* __restrict__ bias,
                                                float* __restrict__ out) {
    char* smem_c = smem_dyn;
    uint32_t smem_base = smem_u32(smem_c);
    int tid = threadIdx.x, wid = tid >> 5, lane = tid & 31;
    int blk = blockIdx.x;
    int b = blk >> 7, h = blk & 127;
    const float* xb = x + (size_t)b * C * HW;
    float2* sTap = (float2*)(smem_c + OFF_TAP);

    // tap tables: per (tap, px): 4 corners, packed (weight, idx)
    for (int i = tid; i < 9*128; i += 256) {
        int tap = i >> 7, px = i & 127;
        size_t sp = (size_t)h*W + px;
        float offy = __ldg(g_offs + ((size_t)(b*18 + tap*2 + 1))*HW + sp);
        float offx = __ldg(g_offs + ((size_t)(b*18 + tap*2 + 0))*HW + sp);
        float m    = __ldg(g_modu + ((size_t)(b*9 + tap))*HW + sp);
        float sy = (float)h  + (float)(tap/3 - 1) + offy;
        float sx2 = (float)px + (float)(tap%3 - 1) + offx;
        float y0f = floorf(sy), x0f = floorf(sx2);
        int y0 = (int)y0f, x0 = (int)x0f;
        float wy1 = sy - y0f, wx1 = sx2 - x0f;
        float wy0 = 1.f - wy1, wx0 = 1.f - wx1;
        #pragma unroll
        for (int cn = 0; cn < 4; cn++) {
            int yy = y0 + (cn >> 1);
            int xx = x0 + (cn & 1);
            float wgt = ((cn & 2) ? wy1 : wy0) * ((cn & 1) ? wx1 : wx0) * m;
            bool valid = ((unsigned)yy < H) && ((unsigned)xx < W);
            int yc = min(max(yy, 0), H-1);
            int xc = min(max(xx, 0), W-1);
            sTap[(tap*4 + cn)*128 + px] = make_float2(valid ? wgt : 0.f,
                                                      __int_as_float(yc*W + xc));
        }
    }

    int wco = (wid >> 1) * 32;
    int wpx = (wid & 1) * 64;
    float acc[2][8][4];
    #pragma unroll
    for (int mt = 0; mt < 2; mt++)
        #pragma unroll
        for (int nt = 0; nt < 8; nt++)
            #pragma unroll
            for (int q = 0; q < 4; q++) acc[mt][nt][q] = 0.f;

    int px = tid & 127, kh = tid >> 7;
    __syncthreads();

    for (int ck = 0; ck < NCHUNK; ck++) {
        if (ck) __syncthreads();
        {
            const uint4* sa = (const uint4*)(g_w4 + (size_t)ck*COUT*SK);
            uint4* da = (uint4*)(smem_c + OFF_A);
            for (int i = tid; i < COUT*SK/8; i += 256) da[i] = sa[i];
        }
        // B build: tap-outer, channel-inner (tables loaded once per tap)
        int k0h = ck*KC + kh*32;
        #pragma unroll
        for (int t = 0; t < 9; t++) {
            float2 t0 = sTap[(t*4 + 0)*128 + px];
            float2 t1 = sTap[(t*4 + 1)*128 + px];
            float2 t2 = sTap[(t*4 + 2)*128 + px];
            float2 t3 = sTap[(t*4 + 3)*128 + px];
            int i0 = __float_as_int(t0.y), i1 = __float_as_int(t1.y);
            int i2 = __float_as_int(t2.y), i3 = __float_as_int(t3.y);
            int clo = (k0h - t + 8) / 9;
            int chi = (k0h + 31 - t) / 9;
            for (int c = clo; c <= chi; c++) {
                const float* xc = xb + (size_t)c*HW;
                float v = t0.x * __ldg(xc + i0);
                v = fmaf(t1.x, __ldg(xc + i1), v);
                v = fmaf(t2.x, __ldg(xc + i2), v);
                v = fmaf(t3.x, __ldg(xc + i3), v);
                int kk = c*9 + t - ck*KC;
                *(unsigned short*)(smem_c + OFF_B + kk*(SKB*2) + px*2) = h_bits(v);
            }
        }
        __syncthreads();
        mma_chunk(smem_base, lane, wco, wpx, acc);
    }

    int g = lane >> 2, tg = lane & 3;
    float* dst = out + (size_t)b*COUT*HW + (size_t)h*W;
    #pragma unroll
    for (int mt = 0; mt < 2; mt++) {
        int co0 = wco + mt*16 + g;
        int co1 = co0 + 8;
        float bv0 = __ldg(bias + co0);
        float bv1 = __ldg(bias + co1);
        #pragma unroll
        for (int nt = 0; nt < 8; nt++) {
            int p2 = wpx + nt*8 + 2*tg;
            *(float2*)(dst + (size_t)co0*HW + p2) = make_float2(acc[mt][nt][0]+bv0, acc[mt][nt][1]+bv0);
            *(float2*)(dst + (size_t)co1*HW + p2) = make_float2(acc[mt][nt][2]+bv1, acc[mt][nt][3]+bv1);
        }
    }
}

// ---------------- launch ----------------
extern "C" void kernel_launch(void* const* d_in, const int* in_sizes, int n_in,
                              void* d_out, int out_size) {
    const float* x        = (const float*)d_in[0];
    const float* weight   = (const float*)d_in[1];
    const float* bias     = (const float*)d_in[2];
    const float* off_w1   = (const float*)d_in[3];
    const float* off_b1   = (const float*)d_in[4];
    const float* off_g    = (const float*)d_in[5];
    const float* off_be   = (const float*)d_in[6];
    const float* off_w2   = (const float*)d_in[7];
    const float* off_b2   = (const float*)d_in[8];
    const float* mod_w1   = (const float*)d_in[9];
    const float* mod_b1   = (const float*)d_in[10];
    const float* mod_g    = (const float*)d_in[11];
    const float* mod_be   = (const float*)d_in[12];
    const float* mod_w2   = (const float*)d_in[13];
    const float* mod_b2   = (const float*)d_in[14];
    float* out = (float*)d_out;

    cudaFuncSetAttribute(conv1_t, cudaFuncAttributeMaxDynamicSharedMemorySize, SMEM_C1);
    cudaFuncSetAttribute(deform_t, cudaFuncAttributeMaxDynamicSharedMemorySize, SMEM_DEF);

    float *offs_ptr, *modu_ptr;
    cudaGetSymbolAddress((void**)&offs_ptr, g_offs);
    cudaGetSymbolAddress((void**)&modu_ptr, g_modu);

    prep_weights<<<(NCHUNK*COUT*KC + 255)/256, 256>>>(off_w1, mod_w1, weight);
    conv1_t<<<1024, 256, SMEM_C1>>>(x, off_b1, mod_b1);
    bn_stats<<<128, 256>>>(off_g, off_be, mod_g, mod_be);
    conv2_all<<<dim3(128, 3), 256>>>(off_w2, off_b2, mod_w2, mod_b2, offs_ptr, modu_ptr);
    deform_t<<<1024, 256, SMEM_DEF>>>(x, bias, out);
}